// round 2
// baseline (speedup 1.0000x reference)
#include <cuda_runtime.h>
#include <cstdint>

#define BQ 4096   // batch
#define ZD 512    // Z
#define HD 384    // H
#define KD2 768   // 2H (K of GEMM2/3)
#define NOUT 896  // Z + H (fused GEMM2/3 N)

// Scratch state (ping-pong) — __device__ globals, allocation-free.
__device__ float g_z[2][(size_t)BQ * ZD];   // z state
__device__ float g_h[2][(size_t)BQ * HD];   // h state
__device__ float g_a[(size_t)BQ * HD];      // lrelu(z@W1^T+b1)

__device__ __forceinline__ float lrelu(float x) { return x > 0.f ? x : 0.01f * x; }

// Prologue: copy inputs into state buffers, zero the t=0 output rows.
__global__ void init_kernel(const float* __restrict__ z, const float* __restrict__ hin,
                            float* __restrict__ out, int T)
{
    int idx = blockIdx.x * blockDim.x + threadIdx.x;
    if (idx < BQ * ZD) {
        g_z[0][idx] = z[idx];
        int m = idx >> 9;          // / ZD
        int n = idx & (ZD - 1);
        out[((size_t)m * T) * ZD + n] = 0.f;   // out[b, 0, :] = 0
    }
    if (idx < BQ * HD) g_h[0][idx] = hin[idx];
}

// GEMM1: g_a = lrelu(g_z[parity] @ W1^T + b1)   M=BQ, N=HD, K=ZD
__global__ __launch_bounds__(256) void gemm1_kernel(const float* __restrict__ W1,
                                                    const float* __restrict__ b1,
                                                    int parity)
{
    __shared__ float As[16][64];
    __shared__ float Bs[16][64];
    const float* __restrict__ Zc = g_z[parity];

    const int row0 = blockIdx.y * 64;
    const int col0 = blockIdx.x * 64;
    const int tid  = threadIdx.x;
    const int lr   = tid >> 2;          // 0..63
    const int lk   = (tid & 3) << 2;    // 0,4,8,12
    const int tx   = tid & 15;
    const int ty   = tid >> 4;

    float acc[4][4] = {};

    for (int k0 = 0; k0 < ZD; k0 += 16) {
        float4 av = *(const float4*)(Zc + (size_t)(row0 + lr) * ZD + k0 + lk);
        float4 bv = *(const float4*)(W1 + (size_t)(col0 + lr) * ZD + k0 + lk);
        As[lk + 0][lr] = av.x; As[lk + 1][lr] = av.y;
        As[lk + 2][lr] = av.z; As[lk + 3][lr] = av.w;
        Bs[lk + 0][lr] = bv.x; Bs[lk + 1][lr] = bv.y;
        Bs[lk + 2][lr] = bv.z; Bs[lk + 3][lr] = bv.w;
        __syncthreads();
#pragma unroll
        for (int k = 0; k < 16; k++) {
            float4 a4 = *(const float4*)&As[k][ty * 4];
            float4 b4 = *(const float4*)&Bs[k][tx * 4];
            float aa[4] = {a4.x, a4.y, a4.z, a4.w};
            float bb[4] = {b4.x, b4.y, b4.z, b4.w};
#pragma unroll
            for (int i = 0; i < 4; i++)
#pragma unroll
                for (int j = 0; j < 4; j++) acc[i][j] += aa[i] * bb[j];
        }
        __syncthreads();
    }

#pragma unroll
    for (int i = 0; i < 4; i++) {
        int m = row0 + ty * 4 + i;
#pragma unroll
        for (int j = 0; j < 4; j++) {
            int n = col0 + tx * 4 + j;
            g_a[(size_t)m * HD + n] = lrelu(acc[i][j] + b1[n]);
        }
    }
}

// GEMM2/3 fused: temp = [g_a | g_h[parity]]  (K=768)
//   n <  512: z_next = lrelu(temp@W2^T+b2)*r + z_cur ; out[m,t,n] = z_next - z0
//   n >= 512: h_next = lrelu(temp@W3^T+b3)*r + h_cur
__global__ __launch_bounds__(256) void gemm2_kernel(const float* __restrict__ W2,
                                                    const float* __restrict__ b2,
                                                    const float* __restrict__ W3,
                                                    const float* __restrict__ b3,
                                                    const float* __restrict__ z0,
                                                    float* __restrict__ out,
                                                    int parity, int t, float r, int T)
{
    __shared__ float As[16][64];
    __shared__ float Bs[16][64];

    const int row0 = blockIdx.y * 64;
    const int col0 = blockIdx.x * 64;
    const bool is_z = (blockIdx.x < (ZD / 64));   // column blocks never straddle 512
    const float* __restrict__ W    = is_z ? W2 : W3;
    const float* __restrict__ bias = is_z ? b2 : b3;
    const int nbase = is_z ? 0 : ZD;
    const float* __restrict__ hcur = g_h[parity];

    const int tid = threadIdx.x;
    const int lr  = tid >> 2;
    const int lk  = (tid & 3) << 2;
    const int tx  = tid & 15;
    const int ty  = tid >> 4;

    float acc[4][4] = {};

    for (int k0 = 0; k0 < KD2; k0 += 16) {
        // temp operand: first HD columns come from g_a, rest from h state.
        // (16-wide k-tiles never straddle k=384 since 384 % 16 == 0)
        const float* Ap = (k0 < HD)
            ? (g_a  + (size_t)(row0 + lr) * HD + k0 + lk)
            : (hcur + (size_t)(row0 + lr) * HD + (k0 - HD) + lk);
        float4 av = *(const float4*)Ap;
        float4 bv = *(const float4*)(W + (size_t)(col0 - nbase + lr) * KD2 + k0 + lk);
        As[lk + 0][lr] = av.x; As[lk + 1][lr] = av.y;
        As[lk + 2][lr] = av.z; As[lk + 3][lr] = av.w;
        Bs[lk + 0][lr] = bv.x; Bs[lk + 1][lr] = bv.y;
        Bs[lk + 2][lr] = bv.z; Bs[lk + 3][lr] = bv.w;
        __syncthreads();
#pragma unroll
        for (int k = 0; k < 16; k++) {
            float4 a4 = *(const float4*)&As[k][ty * 4];
            float4 b4 = *(const float4*)&Bs[k][tx * 4];
            float aa[4] = {a4.x, a4.y, a4.z, a4.w};
            float bb[4] = {b4.x, b4.y, b4.z, b4.w};
#pragma unroll
            for (int i = 0; i < 4; i++)
#pragma unroll
                for (int j = 0; j < 4; j++) acc[i][j] += aa[i] * bb[j];
        }
        __syncthreads();
    }

    float* __restrict__ znext = g_z[parity ^ 1];
    float* __restrict__ hnext = g_h[parity ^ 1];
    const float* __restrict__ zcur = g_z[parity];

#pragma unroll
    for (int i = 0; i < 4; i++) {
        int m = row0 + ty * 4 + i;
#pragma unroll
        for (int j = 0; j < 4; j++) {
            int n = col0 + tx * 4 + j;
            float v = lrelu(acc[i][j] + bias[n - nbase]);
            if (is_z) {
                float val = v * r + zcur[(size_t)m * ZD + n];
                znext[(size_t)m * ZD + n] = val;
                out[((size_t)m * T + t) * ZD + n] = val - z0[(size_t)m * ZD + n];
            } else {
                int nh = n - ZD;
                hnext[(size_t)m * HD + nh] = v * r + hcur[(size_t)m * HD + nh];
            }
        }
    }
}

extern "C" void kernel_launch(void* const* d_in, const int* in_sizes, int n_in,
                              void* d_out, int out_size)
{
    const float* z   = (const float*)d_in[0];
    const float* h0  = (const float*)d_in[1];
    const float* W1  = (const float*)d_in[2];
    const float* b1  = (const float*)d_in[3];
    const float* W2  = (const float*)d_in[4];
    const float* b2  = (const float*)d_in[5];
    const float* W3  = (const float*)d_in[6];
    const float* b3  = (const float*)d_in[7];
    float* out = (float*)d_out;

    const int T = out_size / (BQ * ZD);           // host-side; no device reads needed
    const float r = 0.2f * 4.0f / (float)T;

    init_kernel<<<(BQ * ZD + 255) / 256, 256>>>(z, h0, out, T);

    int parity = 0;
    for (int t = 1; t < T; t++) {
        gemm1_kernel<<<dim3(HD / 64, BQ / 64), 256>>>(W1, b1, parity);
        gemm2_kernel<<<dim3(NOUT / 64, BQ / 64), 256>>>(W2, b2, W3, b3, z, out,
                                                        parity, t, r, T);
        parity ^= 1;
    }
}

// round 5
// speedup vs baseline: 2.1922x; 2.1922x over previous
#include <cuda_runtime.h>
#include <cuda_bf16.h>
#include <cstdint>

#define BQ 4096
#define ZD 512
#define HD 384
#define KD2 768
#define KC 32

// ---------------- device state ----------------
__device__ float g_z[2][(size_t)BQ * ZD];
__device__ float g_h[2][(size_t)BQ * HD];
__device__ __nv_bfloat16 g_zh[2][(size_t)BQ * ZD];
__device__ __nv_bfloat16 g_zl[2][(size_t)BQ * ZD];
__device__ __nv_bfloat16 g_hh[2][(size_t)BQ * HD];
__device__ __nv_bfloat16 g_hl[2][(size_t)BQ * HD];
__device__ __nv_bfloat16 g_ah[(size_t)BQ * HD];
__device__ __nv_bfloat16 g_al[(size_t)BQ * HD];
__device__ __nv_bfloat16 g_w1h[(size_t)HD * ZD], g_w1l[(size_t)HD * ZD];
__device__ __nv_bfloat16 g_w2h[(size_t)ZD * KD2], g_w2l[(size_t)ZD * KD2];
__device__ __nv_bfloat16 g_w3h[(size_t)HD * KD2], g_w3l[(size_t)HD * KD2];

// ---------------- helpers ----------------
__device__ __forceinline__ uint32_t smem_to_u32(const void* p) {
    uint32_t a;
    asm("{ .reg .u64 t; cvta.to.shared.u64 t, %1; cvt.u32.u64 %0, t; }" : "=r"(a) : "l"(p));
    return a;
}
__device__ __forceinline__ float lrelu(float x) { return x > 0.f ? x : 0.01f * x; }
__device__ __forceinline__ uint32_t pack_bf2(float a, float b) {
    uint32_t r;
    asm("cvt.rn.bf16x2.f32 %0, %1, %2;" : "=r"(r) : "f"(b), "f"(a));
    return r;
}
__device__ __forceinline__ void split_bf(float v, __nv_bfloat16& h, __nv_bfloat16& l) {
    h = __float2bfloat16(v);
    l = __float2bfloat16(v - __bfloat162float(h));
}

#define CP_ASYNC16(dst, src) \
    asm volatile("cp.async.cg.shared.global [%0], [%1], 16;" \
                 :: "r"(dst), "l"((unsigned long long)__cvta_generic_to_global(src)) : "memory")
#define CP_COMMIT() asm volatile("cp.async.commit_group;" ::: "memory")

#define LDSM_X4(r0, r1, r2, r3, addr) \
    asm volatile("ldmatrix.sync.aligned.m8n8.x4.shared.b16 {%0,%1,%2,%3}, [%4];" \
                 : "=r"(r0), "=r"(r1), "=r"(r2), "=r"(r3) : "r"(addr))

#define MMA_BF16(c, a, b) \
    asm volatile("mma.sync.aligned.m16n8k16.row.col.f32.bf16.bf16.f32 " \
                 "{%0,%1,%2,%3}, {%4,%5,%6,%7}, {%8,%9}, {%0,%1,%2,%3};" \
                 : "+f"((c)[0]), "+f"((c)[1]), "+f"((c)[2]), "+f"((c)[3]) \
                 : "r"((a)[0]), "r"((a)[1]), "r"((a)[2]), "r"((a)[3]), \
                   "r"((b)[0]), "r"((b)[1]))

// ---------------- prep / init ----------------
__global__ void prep_weights(const float* __restrict__ W1, const float* __restrict__ W2,
                             const float* __restrict__ W3)
{
    int i = blockIdx.x * 256 + threadIdx.x;
    const int s1 = HD * ZD, s2 = ZD * KD2, s3 = HD * KD2;
    if (i < s1) { __nv_bfloat16 h, l; split_bf(W1[i], h, l); g_w1h[i] = h; g_w1l[i] = l; }
    else if (i < s1 + s2) { int j = i - s1; __nv_bfloat16 h, l; split_bf(W2[j], h, l); g_w2h[j] = h; g_w2l[j] = l; }
    else if (i < s1 + s2 + s3) { int j = i - s1 - s2; __nv_bfloat16 h, l; split_bf(W3[j], h, l); g_w3h[j] = h; g_w3l[j] = l; }
}

__global__ void init_kernel(const float* __restrict__ z, const float* __restrict__ hin,
                            float* __restrict__ out, int T)
{
    int idx = blockIdx.x * blockDim.x + threadIdx.x;
    if (idx < BQ * ZD) {
        float v = z[idx];
        g_z[0][idx] = v;
        __nv_bfloat16 h, l; split_bf(v, h, l);
        g_zh[0][idx] = h; g_zl[0][idx] = l;
        int m = idx >> 9, n = idx & (ZD - 1);
        out[((size_t)m * T) * ZD + n] = 0.f;
    }
    if (idx < BQ * HD) {
        float v = hin[idx];
        g_h[0][idx] = v;
        __nv_bfloat16 h, l; split_bf(v, h, l);
        g_hh[0][idx] = h; g_hl[0][idx] = l;
    }
}

// ---------------- tensor-core GEMM (mma.sync bf16 split) ----------------
// smem: 2 stages x 4 tiles (Ah, Al, Bh, Bl), each tile 128 rows x 80B pitch (64B data)
#define TPITCH 80
#define TILE_B (128 * TPITCH)       // 10240
#define STAGE_B (4 * TILE_B)        // 40960
#define SMEM_TOTAL (2 * STAGE_B)    // 81920

__global__ __launch_bounds__(128, 2)
void rec_gemm(int kind, int parity, int t, float r,
              const float* __restrict__ b1, const float* __restrict__ b2,
              const float* __restrict__ b3, const float* __restrict__ z0,
              float* __restrict__ out, int T)
{
    extern __shared__ char smem[];
    const uint32_t sb = smem_to_u32(smem);
    const int tid = threadIdx.x;
    const int wid = tid >> 5, lane = tid & 31;
    const int wm = (wid >> 1) * 64;      // warp m offset in tile
    const int wn = (wid & 1) * 64;       // warp n offset in tile
    const int n0 = blockIdx.x * 128;
    const int row0 = blockIdx.y * 128;
    const bool is_z = (n0 < ZD);
    const int NCH = kind ? (KD2 / KC) : (ZD / KC);

    // B (weights) source
    const __nv_bfloat16 *Bh, *Bl;
    int bs;
    if (kind == 0)  { Bh = g_w1h + (size_t)n0 * ZD;         Bl = g_w1l + (size_t)n0 * ZD;         bs = ZD; }
    else if (is_z)  { Bh = g_w2h + (size_t)n0 * KD2;        Bl = g_w2l + (size_t)n0 * KD2;        bs = KD2; }
    else            { Bh = g_w3h + (size_t)(n0 - ZD) * KD2; Bl = g_w3l + (size_t)(n0 - ZD) * KD2; bs = KD2; }

    float acc[4][8][4];
#pragma unroll
    for (int i = 0; i < 4; i++)
#pragma unroll
        for (int j = 0; j < 8; j++)
#pragma unroll
            for (int k = 0; k < 4; k++) acc[i][j][k] = 0.f;

    // per-lane ldmatrix address components
    const int a_row = wm + (lane & 7) + ((lane >> 3) & 1) * 8;
    const uint32_t a_koff = (uint32_t)(lane >> 4) * 16;
    const int b_row = wn + (lane & 7) + (lane >> 4) * 8;
    const uint32_t b_koff = (uint32_t)((lane >> 3) & 1) * 16;

    auto issue = [&](int c) {
        const int kc = c * KC;
        const __nv_bfloat16 *Ah, *Al;
        int kA, as_;
        if (kind == 0) {
            Ah = g_zh[parity] + (size_t)row0 * ZD; Al = g_zl[parity] + (size_t)row0 * ZD;
            kA = kc; as_ = ZD;
        } else if (kc < HD) {
            Ah = g_ah + (size_t)row0 * HD; Al = g_al + (size_t)row0 * HD;
            kA = kc; as_ = HD;
        } else {
            Ah = g_hh[parity] + (size_t)row0 * HD; Al = g_hl[parity] + (size_t)row0 * HD;
            kA = kc - HD; as_ = HD;
        }
        const uint32_t stg = sb + (uint32_t)(c & 1) * STAGE_B;
#pragma unroll
        for (int i = 0; i < 16; i++) {
            int g = i * 128 + tid;                  // 0..2047
            int tile = g >> 9;                      // 0:Ah 1:Al 2:Bh 3:Bl
            int j = g & 511;
            int row = j >> 2, c4 = j & 3;
            uint32_t dst = stg + (uint32_t)tile * TILE_B + (uint32_t)row * TPITCH + (uint32_t)c4 * 16;
            const __nv_bfloat16* srcp;
            if (tile == 0)      srcp = Ah + (size_t)row * as_ + kA + c4 * 8;
            else if (tile == 1) srcp = Al + (size_t)row * as_ + kA + c4 * 8;
            else if (tile == 2) srcp = Bh + (size_t)row * bs + kc + c4 * 8;
            else                srcp = Bl + (size_t)row * bs + kc + c4 * 8;
            CP_ASYNC16(dst, srcp);
        }
        CP_COMMIT();
    };

    issue(0);
    for (int c = 0; c < NCH; c++) {
        if (c + 1 < NCH) {
            issue(c + 1);
            asm volatile("cp.async.wait_group 1;" ::: "memory");
        } else {
            asm volatile("cp.async.wait_group 0;" ::: "memory");
        }
        __syncthreads();
        const uint32_t stg = sb + (uint32_t)(c & 1) * STAGE_B;
#pragma unroll
        for (int kk = 0; kk < 2; kk++) {
            const uint32_t kb = (uint32_t)kk * 32;
            uint32_t Ahf[4][4], Alf[4][4], Bhf[8][2], Blf[8][2];
#pragma unroll
            for (int mf = 0; mf < 4; mf++) {
                uint32_t ad = stg + (uint32_t)(a_row + mf * 16) * TPITCH + kb + a_koff;
                LDSM_X4(Ahf[mf][0], Ahf[mf][1], Ahf[mf][2], Ahf[mf][3], ad);
                LDSM_X4(Alf[mf][0], Alf[mf][1], Alf[mf][2], Alf[mf][3], ad + TILE_B);
            }
#pragma unroll
            for (int nb = 0; nb < 4; nb++) {
                uint32_t bd = stg + 2 * TILE_B + (uint32_t)(b_row + nb * 16) * TPITCH + kb + b_koff;
                LDSM_X4(Bhf[nb * 2][0], Bhf[nb * 2][1], Bhf[nb * 2 + 1][0], Bhf[nb * 2 + 1][1], bd);
                LDSM_X4(Blf[nb * 2][0], Blf[nb * 2][1], Blf[nb * 2 + 1][0], Blf[nb * 2 + 1][1], bd + TILE_B);
            }
#pragma unroll
            for (int mf = 0; mf < 4; mf++)
#pragma unroll
                for (int nf = 0; nf < 8; nf++) {
                    MMA_BF16(acc[mf][nf], Ahf[mf], Bhf[nf]);
                    MMA_BF16(acc[mf][nf], Ahf[mf], Blf[nf]);
                    MMA_BF16(acc[mf][nf], Alf[mf], Bhf[nf]);
                }
        }
        __syncthreads();
    }

    // ---------------- epilogue ----------------
    const int quad = lane >> 2, tq = (lane & 3) * 2;
#pragma unroll
    for (int mf = 0; mf < 4; mf++) {
        const int rb = row0 + wm + mf * 16 + quad;
#pragma unroll
        for (int nf = 0; nf < 8; nf++) {
            const int n = n0 + wn + nf * 8 + tq;
#pragma unroll
            for (int half = 0; half < 2; half++) {
                const int m = rb + half * 8;
                const float c0 = acc[mf][nf][half * 2 + 0];
                const float c1 = acc[mf][nf][half * 2 + 1];
                if (kind == 0) {
                    float v0 = lrelu(c0 + b1[n]);
                    float v1 = lrelu(c1 + b1[n + 1]);
                    float h0 = __bfloat162float(__float2bfloat16(v0));
                    float h1 = __bfloat162float(__float2bfloat16(v1));
                    *(uint32_t*)(g_ah + (size_t)m * HD + n) = pack_bf2(h0, h1);
                    *(uint32_t*)(g_al + (size_t)m * HD + n) = pack_bf2(v0 - h0, v1 - h1);
                } else if (is_z) {
                    float2 zv = *(const float2*)(g_z[parity] + (size_t)m * ZD + n);
                    float2 ov = *(const float2*)(z0 + (size_t)m * ZD + n);
                    float v0 = lrelu(c0 + b2[n]) * r + zv.x;
                    float v1 = lrelu(c1 + b2[n + 1]) * r + zv.y;
                    *(float2*)(g_z[parity ^ 1] + (size_t)m * ZD + n) = make_float2(v0, v1);
                    *(float2*)(out + ((size_t)m * T + t) * ZD + n) = make_float2(v0 - ov.x, v1 - ov.y);
                    float h0 = __bfloat162float(__float2bfloat16(v0));
                    float h1 = __bfloat162float(__float2bfloat16(v1));
                    *(uint32_t*)(g_zh[parity ^ 1] + (size_t)m * ZD + n) = pack_bf2(h0, h1);
                    *(uint32_t*)(g_zl[parity ^ 1] + (size_t)m * ZD + n) = pack_bf2(v0 - h0, v1 - h1);
                } else {
                    const int nh = n - ZD;
                    float2 hv = *(const float2*)(g_h[parity] + (size_t)m * HD + nh);
                    float v0 = lrelu(c0 + b3[nh]) * r + hv.x;
                    float v1 = lrelu(c1 + b3[nh + 1]) * r + hv.y;
                    *(float2*)(g_h[parity ^ 1] + (size_t)m * HD + nh) = make_float2(v0, v1);
                    float h0 = __bfloat162float(__float2bfloat16(v0));
                    float h1 = __bfloat162float(__float2bfloat16(v1));
                    *(uint32_t*)(g_hh[parity ^ 1] + (size_t)m * HD + nh) = pack_bf2(h0, h1);
                    *(uint32_t*)(g_hl[parity ^ 1] + (size_t)m * HD + nh) = pack_bf2(v0 - h0, v1 - h1);
                }
            }
        }
    }
}

// ---------------- host ----------------
extern "C" void kernel_launch(void* const* d_in, const int* in_sizes, int n_in,
                              void* d_out, int out_size)
{
    const float* z  = (const float*)d_in[0];
    const float* h0 = (const float*)d_in[1];
    const float* W1 = (const float*)d_in[2];
    const float* b1 = (const float*)d_in[3];
    const float* W2 = (const float*)d_in[4];
    const float* b2 = (const float*)d_in[5];
    const float* W3 = (const float*)d_in[6];
    const float* b3 = (const float*)d_in[7];
    float* out = (float*)d_out;

    const int T = out_size / (BQ * ZD);
    const float r = 0.2f * 4.0f / (float)T;

    static int attr_done = 0;
    if (!attr_done) {
        cudaFuncSetAttribute(rec_gemm, cudaFuncAttributeMaxDynamicSharedMemorySize, SMEM_TOTAL);
        attr_done = 1;
    }

    const int wtot = HD * ZD + ZD * KD2 + HD * KD2;
    prep_weights<<<(wtot + 255) / 256, 256>>>(W1, W2, W3);
    init_kernel<<<(BQ * ZD + 255) / 256, 256>>>(z, h0, out, T);

    int parity = 0;
    for (int t = 1; t < T; t++) {
        rec_gemm<<<dim3(HD / 128, BQ / 128), 128, SMEM_TOTAL>>>(0, parity, t, r, b1, b2, b3, z, out, T);
        rec_gemm<<<dim3((ZD + HD) / 128, BQ / 128), 128, SMEM_TOTAL>>>(1, parity, t, r, b1, b2, b3, z, out, T);
        parity ^= 1;
    }
}

// round 6
// speedup vs baseline: 2.7694x; 1.2633x over previous
#include <cuda_runtime.h>
#include <cuda_bf16.h>
#include <cstdint>

#define BQ 4096
#define ZD 512
#define HD 384
#define KD2 768
#define KC 32

// ---------------- device state ----------------
__device__ float g_z[2][(size_t)BQ * ZD];
__device__ float g_h[2][(size_t)BQ * HD];
__device__ __nv_bfloat16 g_zh[2][(size_t)BQ * ZD];
__device__ __nv_bfloat16 g_zl[2][(size_t)BQ * ZD];
__device__ __nv_bfloat16 g_hh[2][(size_t)BQ * HD];
__device__ __nv_bfloat16 g_hl[2][(size_t)BQ * HD];
__device__ __nv_bfloat16 g_ah[(size_t)BQ * HD];
__device__ __nv_bfloat16 g_al[(size_t)BQ * HD];
__device__ __nv_bfloat16 g_w1h[(size_t)HD * ZD], g_w1l[(size_t)HD * ZD];
__device__ __nv_bfloat16 g_w2h[(size_t)ZD * KD2], g_w2l[(size_t)ZD * KD2];
__device__ __nv_bfloat16 g_w3h[(size_t)HD * KD2], g_w3l[(size_t)HD * KD2];

// ---------------- helpers ----------------
__device__ __forceinline__ uint32_t smem_to_u32(const void* p) {
    uint32_t a;
    asm("{ .reg .u64 t; cvta.to.shared.u64 t, %1; cvt.u32.u64 %0, t; }" : "=r"(a) : "l"(p));
    return a;
}
__device__ __forceinline__ float lrelu(float x) { return x > 0.f ? x : 0.01f * x; }
__device__ __forceinline__ uint32_t pack_bf2(float a, float b) {
    uint32_t r;
    asm("cvt.rn.bf16x2.f32 %0, %1, %2;" : "=r"(r) : "f"(b), "f"(a));
    return r;
}
__device__ __forceinline__ void split_bf(float v, __nv_bfloat16& h, __nv_bfloat16& l) {
    h = __float2bfloat16(v);
    l = __float2bfloat16(v - __bfloat162float(h));
}

#define CP_ASYNC16(dst, src) \
    asm volatile("cp.async.cg.shared.global [%0], [%1], 16;" \
                 :: "r"(dst), "l"((unsigned long long)__cvta_generic_to_global(src)) : "memory")
#define CP_COMMIT() asm volatile("cp.async.commit_group;" ::: "memory")

#define LDSM_X4(r0, r1, r2, r3, addr) \
    asm volatile("ldmatrix.sync.aligned.m8n8.x4.shared.b16 {%0,%1,%2,%3}, [%4];" \
                 : "=r"(r0), "=r"(r1), "=r"(r2), "=r"(r3) : "r"(addr))

#define MMA_BF16(c, a, b) \
    asm volatile("mma.sync.aligned.m16n8k16.row.col.f32.bf16.bf16.f32 " \
                 "{%0,%1,%2,%3}, {%4,%5,%6,%7}, {%8,%9}, {%0,%1,%2,%3};" \
                 : "+f"((c)[0]), "+f"((c)[1]), "+f"((c)[2]), "+f"((c)[3]) \
                 : "r"((a)[0]), "r"((a)[1]), "r"((a)[2]), "r"((a)[3]), \
                   "r"((b)[0]), "r"((b)[1]))

// ---------------- prep / init ----------------
__global__ void prep_weights(const float* __restrict__ W1, const float* __restrict__ W2,
                             const float* __restrict__ W3)
{
    int i = blockIdx.x * 256 + threadIdx.x;
    const int s1 = HD * ZD, s2 = ZD * KD2, s3 = HD * KD2;
    if (i < s1) { __nv_bfloat16 h, l; split_bf(W1[i], h, l); g_w1h[i] = h; g_w1l[i] = l; }
    else if (i < s1 + s2) { int j = i - s1; __nv_bfloat16 h, l; split_bf(W2[j], h, l); g_w2h[j] = h; g_w2l[j] = l; }
    else if (i < s1 + s2 + s3) { int j = i - s1 - s2; __nv_bfloat16 h, l; split_bf(W3[j], h, l); g_w3h[j] = h; g_w3l[j] = l; }
}

__global__ void init_kernel(const float* __restrict__ z, const float* __restrict__ hin,
                            float* __restrict__ out, int T)
{
    int idx = blockIdx.x * blockDim.x + threadIdx.x;
    if (idx < BQ * ZD) {
        float v = z[idx];
        g_z[0][idx] = v;
        __nv_bfloat16 h, l; split_bf(v, h, l);
        g_zh[0][idx] = h; g_zl[0][idx] = l;
        int m = idx >> 9, n = idx & (ZD - 1);
        out[((size_t)m * T) * ZD + n] = 0.f;
    }
    if (idx < BQ * HD) {
        float v = hin[idx];
        g_h[0][idx] = v;
        __nv_bfloat16 h, l; split_bf(v, h, l);
        g_hh[0][idx] = h; g_hl[0][idx] = l;
    }
}

// ---------------- tensor-core GEMM (mma.sync bf16 split) ----------------
// Tile 64(M) x 128(N), 128 threads (4 warps, each 32x64), 3 CTAs/SM.
// smem per stage: Ah(64x80) Al(64x80) Bh(128x80) Bl(128x80) = 30720 B, 2 stages.
#define TPITCH 80
#define A_TILE_B (64 * TPITCH)      // 5120
#define B_TILE_B (128 * TPITCH)     // 10240
#define STAGE_B (2 * A_TILE_B + 2 * B_TILE_B)  // 30720
#define SMEM_TOTAL (2 * STAGE_B)               // 61440
#define OFF_AH 0
#define OFF_AL A_TILE_B
#define OFF_BH (2 * A_TILE_B)
#define OFF_BL (2 * A_TILE_B + B_TILE_B)

__global__ __launch_bounds__(128, 3)
void rec_gemm(int kind, int parity, int t, float r,
              const float* __restrict__ b1, const float* __restrict__ b2,
              const float* __restrict__ b3, const float* __restrict__ z0,
              float* __restrict__ out, int T)
{
    extern __shared__ char smem[];
    const uint32_t sb = smem_to_u32(smem);
    const int tid = threadIdx.x;
    const int wid = tid >> 5, lane = tid & 31;
    const int wm = (wid >> 1) * 32;      // warp m offset in tile (0/32)
    const int wn = (wid & 1) * 64;       // warp n offset in tile (0/64)
    const int n0 = blockIdx.x * 128;
    const int row0 = blockIdx.y * 64;
    const bool is_z = (n0 < ZD);
    const int NCH = kind ? (KD2 / KC) : (ZD / KC);

    // B (weights) source
    const __nv_bfloat16 *Bh, *Bl;
    int bs;
    if (kind == 0)  { Bh = g_w1h + (size_t)n0 * ZD;         Bl = g_w1l + (size_t)n0 * ZD;         bs = ZD; }
    else if (is_z)  { Bh = g_w2h + (size_t)n0 * KD2;        Bl = g_w2l + (size_t)n0 * KD2;        bs = KD2; }
    else            { Bh = g_w3h + (size_t)(n0 - ZD) * KD2; Bl = g_w3l + (size_t)(n0 - ZD) * KD2; bs = KD2; }

    float acc[2][8][4];
#pragma unroll
    for (int i = 0; i < 2; i++)
#pragma unroll
        for (int j = 0; j < 8; j++)
#pragma unroll
            for (int k = 0; k < 4; k++) acc[i][j][k] = 0.f;

    // per-lane ldmatrix address components
    const int a_row = wm + (lane & 7) + ((lane >> 3) & 1) * 8;
    const uint32_t a_koff = (uint32_t)(lane >> 4) * 16;
    const int b_row = wn + (lane & 7) + (lane >> 4) * 8;
    const uint32_t b_koff = (uint32_t)((lane >> 3) & 1) * 16;

    auto issue = [&](int c) {
        const int kc = c * KC;
        const __nv_bfloat16 *Ah, *Al;
        int kA, as_;
        if (kind == 0) {
            Ah = g_zh[parity] + (size_t)row0 * ZD; Al = g_zl[parity] + (size_t)row0 * ZD;
            kA = kc; as_ = ZD;
        } else if (kc < HD) {
            Ah = g_ah + (size_t)row0 * HD; Al = g_al + (size_t)row0 * HD;
            kA = kc; as_ = HD;
        } else {
            Ah = g_hh[parity] + (size_t)row0 * HD; Al = g_hl[parity] + (size_t)row0 * HD;
            kA = kc - HD; as_ = HD;
        }
        const uint32_t stg = sb + (uint32_t)(c & 1) * STAGE_B;
        // 1536 16B-vectors total: Ah 256, Al 256, Bh 512, Bl 512 -> 12 per thread
#pragma unroll
        for (int i = 0; i < 12; i++) {
            int g = i * 128 + tid;
            uint32_t dst;
            const __nv_bfloat16* srcp;
            if (g < 256) {
                int row = g >> 2, c4 = g & 3;
                dst = stg + OFF_AH + (uint32_t)row * TPITCH + (uint32_t)c4 * 16;
                srcp = Ah + (size_t)row * as_ + kA + c4 * 8;
            } else if (g < 512) {
                int j = g - 256, row = j >> 2, c4 = j & 3;
                dst = stg + OFF_AL + (uint32_t)row * TPITCH + (uint32_t)c4 * 16;
                srcp = Al + (size_t)row * as_ + kA + c4 * 8;
            } else if (g < 1024) {
                int j = g - 512, row = j >> 2, c4 = j & 3;
                dst = stg + OFF_BH + (uint32_t)row * TPITCH + (uint32_t)c4 * 16;
                srcp = Bh + (size_t)row * bs + kc + c4 * 8;
            } else {
                int j = g - 1024, row = j >> 2, c4 = j & 3;
                dst = stg + OFF_BL + (uint32_t)row * TPITCH + (uint32_t)c4 * 16;
                srcp = Bl + (size_t)row * bs + kc + c4 * 8;
            }
            CP_ASYNC16(dst, srcp);
        }
        CP_COMMIT();
    };

    issue(0);
    for (int c = 0; c < NCH; c++) {
        if (c + 1 < NCH) {
            issue(c + 1);
            asm volatile("cp.async.wait_group 1;" ::: "memory");
        } else {
            asm volatile("cp.async.wait_group 0;" ::: "memory");
        }
        __syncthreads();
        const uint32_t stg = sb + (uint32_t)(c & 1) * STAGE_B;
#pragma unroll
        for (int kk = 0; kk < 2; kk++) {
            const uint32_t kb = (uint32_t)kk * 32;
            uint32_t Ahf[2][4], Alf[2][4], Bhf[8][2], Blf[8][2];
#pragma unroll
            for (int mf = 0; mf < 2; mf++) {
                uint32_t ad = stg + OFF_AH + (uint32_t)(a_row + mf * 16) * TPITCH + kb + a_koff;
                LDSM_X4(Ahf[mf][0], Ahf[mf][1], Ahf[mf][2], Ahf[mf][3], ad);
                LDSM_X4(Alf[mf][0], Alf[mf][1], Alf[mf][2], Alf[mf][3], ad + A_TILE_B);
            }
#pragma unroll
            for (int nb = 0; nb < 4; nb++) {
                uint32_t bd = stg + OFF_BH + (uint32_t)(b_row + nb * 16) * TPITCH + kb + b_koff;
                LDSM_X4(Bhf[nb * 2][0], Bhf[nb * 2][1], Bhf[nb * 2 + 1][0], Bhf[nb * 2 + 1][1], bd);
                LDSM_X4(Blf[nb * 2][0], Blf[nb * 2][1], Blf[nb * 2 + 1][0], Blf[nb * 2 + 1][1], bd + B_TILE_B);
            }
            // term-major order: same-acc reuses are 15 MMAs apart (ILP)
#pragma unroll
            for (int mf = 0; mf < 2; mf++)
#pragma unroll
                for (int nf = 0; nf < 8; nf++) MMA_BF16(acc[mf][nf], Ahf[mf], Bhf[nf]);
#pragma unroll
            for (int mf = 0; mf < 2; mf++)
#pragma unroll
                for (int nf = 0; nf < 8; nf++) MMA_BF16(acc[mf][nf], Ahf[mf], Blf[nf]);
#pragma unroll
            for (int mf = 0; mf < 2; mf++)
#pragma unroll
                for (int nf = 0; nf < 8; nf++) MMA_BF16(acc[mf][nf], Alf[mf], Bhf[nf]);
        }
        __syncthreads();
    }

    // ---------------- epilogue ----------------
    const int quad = lane >> 2, tq = (lane & 3) * 2;
#pragma unroll
    for (int mf = 0; mf < 2; mf++) {
        const int rb = row0 + wm + mf * 16 + quad;
#pragma unroll
        for (int nf = 0; nf < 8; nf++) {
            const int n = n0 + wn + nf * 8 + tq;
#pragma unroll
            for (int half = 0; half < 2; half++) {
                const int m = rb + half * 8;
                const float c0 = acc[mf][nf][half * 2 + 0];
                const float c1 = acc[mf][nf][half * 2 + 1];
                if (kind == 0) {
                    float v0 = lrelu(c0 + b1[n]);
                    float v1 = lrelu(c1 + b1[n + 1]);
                    float h0 = __bfloat162float(__float2bfloat16(v0));
                    float h1 = __bfloat162float(__float2bfloat16(v1));
                    *(uint32_t*)(g_ah + (size_t)m * HD + n) = pack_bf2(h0, h1);
                    *(uint32_t*)(g_al + (size_t)m * HD + n) = pack_bf2(v0 - h0, v1 - h1);
                } else if (is_z) {
                    float2 zv = *(const float2*)(g_z[parity] + (size_t)m * ZD + n);
                    float2 ov = *(const float2*)(z0 + (size_t)m * ZD + n);
                    float v0 = lrelu(c0 + b2[n]) * r + zv.x;
                    float v1 = lrelu(c1 + b2[n + 1]) * r + zv.y;
                    *(float2*)(g_z[parity ^ 1] + (size_t)m * ZD + n) = make_float2(v0, v1);
                    *(float2*)(out + ((size_t)m * T + t) * ZD + n) = make_float2(v0 - ov.x, v1 - ov.y);
                    float h0 = __bfloat162float(__float2bfloat16(v0));
                    float h1 = __bfloat162float(__float2bfloat16(v1));
                    *(uint32_t*)(g_zh[parity ^ 1] + (size_t)m * ZD + n) = pack_bf2(h0, h1);
                    *(uint32_t*)(g_zl[parity ^ 1] + (size_t)m * ZD + n) = pack_bf2(v0 - h0, v1 - h1);
                } else {
                    const int nh = n - ZD;
                    float2 hv = *(const float2*)(g_h[parity] + (size_t)m * HD + nh);
                    float v0 = lrelu(c0 + b3[nh]) * r + hv.x;
                    float v1 = lrelu(c1 + b3[nh + 1]) * r + hv.y;
                    *(float2*)(g_h[parity ^ 1] + (size_t)m * HD + nh) = make_float2(v0, v1);
                    float h0 = __bfloat162float(__float2bfloat16(v0));
                    float h1 = __bfloat162float(__float2bfloat16(v1));
                    *(uint32_t*)(g_hh[parity ^ 1] + (size_t)m * HD + nh) = pack_bf2(h0, h1);
                    *(uint32_t*)(g_hl[parity ^ 1] + (size_t)m * HD + nh) = pack_bf2(v0 - h0, v1 - h1);
                }
            }
        }
    }
}

// ---------------- host ----------------
extern "C" void kernel_launch(void* const* d_in, const int* in_sizes, int n_in,
                              void* d_out, int out_size)
{
    const float* z  = (const float*)d_in[0];
    const float* h0 = (const float*)d_in[1];
    const float* W1 = (const float*)d_in[2];
    const float* b1 = (const float*)d_in[3];
    const float* W2 = (const float*)d_in[4];
    const float* b2 = (const float*)d_in[5];
    const float* W3 = (const float*)d_in[6];
    const float* b3 = (const float*)d_in[7];
    float* out = (float*)d_out;

    const int T = out_size / (BQ * ZD);
    const float r = 0.2f * 4.0f / (float)T;

    cudaFuncSetAttribute(rec_gemm, cudaFuncAttributeMaxDynamicSharedMemorySize, SMEM_TOTAL);

    const int wtot = HD * ZD + ZD * KD2 + HD * KD2;
    prep_weights<<<(wtot + 255) / 256, 256>>>(W1, W2, W3);
    init_kernel<<<(BQ * ZD + 255) / 256, 256>>>(z, h0, out, T);

    int parity = 0;
    for (int t = 1; t < T; t++) {
        rec_gemm<<<dim3(HD / 128, BQ / 64), 128, SMEM_TOTAL>>>(0, parity, t, r, b1, b2, b3, z, out, T);
        rec_gemm<<<dim3((ZD + HD) / 128, BQ / 64), 128, SMEM_TOTAL>>>(1, parity, t, r, b1, b2, b3, z, out, T);
        parity ^= 1;
    }
}

// round 7
// speedup vs baseline: 3.3678x; 1.2161x over previous
#include <cuda_runtime.h>
#include <cuda_bf16.h>
#include <cstdint>

#define BQ 4096
#define ZD 512
#define HD 384
#define KD2 768
#define KC 32

// ---------------- device state ----------------
__device__ float g_z[2][(size_t)BQ * ZD];
__device__ float g_h[2][(size_t)BQ * HD];
__device__ __nv_bfloat16 g_zh[2][(size_t)BQ * ZD];
__device__ __nv_bfloat16 g_zl[2][(size_t)BQ * ZD];
__device__ __nv_bfloat16 g_hh[2][(size_t)BQ * HD];
__device__ __nv_bfloat16 g_hl[2][(size_t)BQ * HD];
__device__ __nv_bfloat16 g_ah[(size_t)BQ * HD];
__device__ __nv_bfloat16 g_al[(size_t)BQ * HD];
__device__ __nv_bfloat16 g_w1h[(size_t)HD * ZD], g_w1l[(size_t)HD * ZD];
__device__ __nv_bfloat16 g_w2h[(size_t)ZD * KD2], g_w2l[(size_t)ZD * KD2];
__device__ __nv_bfloat16 g_w3h[(size_t)HD * KD2], g_w3l[(size_t)HD * KD2];

// ---------------- helpers ----------------
__device__ __forceinline__ uint32_t smem_to_u32(const void* p) {
    uint32_t a;
    asm("{ .reg .u64 t; cvta.to.shared.u64 t, %1; cvt.u32.u64 %0, t; }" : "=r"(a) : "l"(p));
    return a;
}
__device__ __forceinline__ float lrelu(float x) { return x > 0.f ? x : 0.01f * x; }
__device__ __forceinline__ uint32_t pack_bf2(float a, float b) {
    uint32_t r;
    asm("cvt.rn.bf16x2.f32 %0, %1, %2;" : "=r"(r) : "f"(b), "f"(a));
    return r;
}
__device__ __forceinline__ void split_bf(float v, __nv_bfloat16& h, __nv_bfloat16& l) {
    h = __float2bfloat16(v);
    l = __float2bfloat16(v - __bfloat162float(h));
}
// XOR swizzle: byte address within a tile for (row, 16B-chunk c)
__device__ __forceinline__ uint32_t swz(uint32_t row, uint32_t c) {
    return row * 64u + ((c ^ ((row >> 1) & 3u)) << 4);
}

#define CP_ASYNC16(dst, src) \
    asm volatile("cp.async.cg.shared.global [%0], [%1], 16;" \
                 :: "r"(dst), "l"((unsigned long long)__cvta_generic_to_global(src)) : "memory")
#define CP_COMMIT() asm volatile("cp.async.commit_group;" ::: "memory")

#define LDSM_X4(r0, r1, r2, r3, addr) \
    asm volatile("ldmatrix.sync.aligned.m8n8.x4.shared.b16 {%0,%1,%2,%3}, [%4];" \
                 : "=r"(r0), "=r"(r1), "=r"(r2), "=r"(r3) : "r"(addr))

#define MMA_BF16(c, a, b) \
    asm volatile("mma.sync.aligned.m16n8k16.row.col.f32.bf16.bf16.f32 " \
                 "{%0,%1,%2,%3}, {%4,%5,%6,%7}, {%8,%9}, {%0,%1,%2,%3};" \
                 : "+f"((c)[0]), "+f"((c)[1]), "+f"((c)[2]), "+f"((c)[3]) \
                 : "r"((a)[0]), "r"((a)[1]), "r"((a)[2]), "r"((a)[3]), \
                   "r"((b)[0]), "r"((b)[1]))

// ---------------- prep / init ----------------
__global__ void prep_weights(const float* __restrict__ W1, const float* __restrict__ W2,
                             const float* __restrict__ W3)
{
    int i = blockIdx.x * 256 + threadIdx.x;
    const int s1 = HD * ZD, s2 = ZD * KD2, s3 = HD * KD2;
    if (i < s1) { __nv_bfloat16 h, l; split_bf(W1[i], h, l); g_w1h[i] = h; g_w1l[i] = l; }
    else if (i < s1 + s2) { int j = i - s1; __nv_bfloat16 h, l; split_bf(W2[j], h, l); g_w2h[j] = h; g_w2l[j] = l; }
    else if (i < s1 + s2 + s3) { int j = i - s1 - s2; __nv_bfloat16 h, l; split_bf(W3[j], h, l); g_w3h[j] = h; g_w3l[j] = l; }
}

__global__ void init_kernel(const float* __restrict__ z, const float* __restrict__ hin,
                            float* __restrict__ out, int T)
{
    int idx = blockIdx.x * blockDim.x + threadIdx.x;
    if (idx < BQ * ZD) {
        float v = z[idx];
        g_z[0][idx] = v;
        __nv_bfloat16 h, l; split_bf(v, h, l);
        g_zh[0][idx] = h; g_zl[0][idx] = l;
        int m = idx >> 9, n = idx & (ZD - 1);
        out[((size_t)m * T) * ZD + n] = 0.f;
    }
    if (idx < BQ * HD) {
        float v = hin[idx];
        g_h[0][idx] = v;
        __nv_bfloat16 h, l; split_bf(v, h, l);
        g_hh[0][idx] = h; g_hl[0][idx] = l;
    }
}

// ---------------- tensor-core GEMM (mma.sync bf16 split) ----------------
// Tile TM(M) x 128(N), 128 threads (4 warps), XOR-swizzled smem (64B row pitch),
// 2-stage cp.async pipeline, 4 CTAs/SM.
template <int TM>
__global__ __launch_bounds__(128, 4)
void rec_gemm(int kind, int parity, int t, float r,
              const float* __restrict__ b1, const float* __restrict__ b2,
              const float* __restrict__ b3, const float* __restrict__ z0,
              float* __restrict__ out, int T)
{
    constexpr int MF = TM / 32;                 // m16 frags per warp
    constexpr int A_TILE_B = TM * 64;           // bytes per A tile
    constexpr int B_TILE_B = 128 * 64;          // 8192
    constexpr int OFF_AH = 0;
    constexpr int OFF_AL = A_TILE_B;
    constexpr int OFF_BH = 2 * A_TILE_B;
    constexpr int OFF_BL = 2 * A_TILE_B + B_TILE_B;
    constexpr int STAGE_B = 2 * A_TILE_B + 2 * B_TILE_B;
    constexpr int NA = TM * 4;                  // 16B chunks per A tile
    constexpr int NVEC = (2 * NA + 1024) / 128; // chunks per thread

    extern __shared__ char smem[];
    const uint32_t sb = smem_to_u32(smem);
    const int tid = threadIdx.x;
    const int wid = tid >> 5, lane = tid & 31;
    const int wm = (wid >> 1) * (TM / 2);       // warp m offset
    const int wn = (wid & 1) * 64;              // warp n offset
    const int n0 = blockIdx.x * 128;
    const int row0 = blockIdx.y * TM;
    const bool is_z = (n0 < ZD);
    const int NCH = kind ? (KD2 / KC) : (ZD / KC);

    const __nv_bfloat16 *Bh, *Bl;
    int bs;
    if (kind == 0)  { Bh = g_w1h + (size_t)n0 * ZD;         Bl = g_w1l + (size_t)n0 * ZD;         bs = ZD; }
    else if (is_z)  { Bh = g_w2h + (size_t)n0 * KD2;        Bl = g_w2l + (size_t)n0 * KD2;        bs = KD2; }
    else            { Bh = g_w3h + (size_t)(n0 - ZD) * KD2; Bl = g_w3l + (size_t)(n0 - ZD) * KD2; bs = KD2; }

    float acc[MF][8][4];
#pragma unroll
    for (int i = 0; i < MF; i++)
#pragma unroll
        for (int j = 0; j < 8; j++)
#pragma unroll
            for (int k = 0; k < 4; k++) acc[i][j][k] = 0.f;

    const int a_row = wm + (lane & 7) + ((lane >> 3) & 1) * 8;
    const uint32_t a_cbit = (uint32_t)(lane >> 4);          // k16 half
    const uint32_t ax = (uint32_t)((a_row >> 1) & 3);
    const int b_row = wn + (lane & 7) + (lane >> 4) * 8;
    const uint32_t b_cbit = (uint32_t)((lane >> 3) & 1);
    const uint32_t bx = (uint32_t)((b_row >> 1) & 3);

    auto issue = [&](int c) {
        const int kc = c * KC;
        const __nv_bfloat16 *Ah, *Al;
        int kA, as_;
        if (kind == 0) {
            Ah = g_zh[parity] + (size_t)row0 * ZD; Al = g_zl[parity] + (size_t)row0 * ZD;
            kA = kc; as_ = ZD;
        } else if (kc < HD) {
            Ah = g_ah + (size_t)row0 * HD; Al = g_al + (size_t)row0 * HD;
            kA = kc; as_ = HD;
        } else {
            Ah = g_hh[parity] + (size_t)row0 * HD; Al = g_hl[parity] + (size_t)row0 * HD;
            kA = kc - HD; as_ = HD;
        }
        const uint32_t stg = sb + (uint32_t)(c & 1) * STAGE_B;
#pragma unroll
        for (int i = 0; i < NVEC; i++) {
            int g = i * 128 + tid;
            uint32_t dst;
            const __nv_bfloat16* srcp;
            if (g < NA) {
                uint32_t row = g >> 2, c4 = g & 3;
                dst = stg + OFF_AH + swz(row, c4);
                srcp = Ah + (size_t)row * as_ + kA + c4 * 8;
            } else if (g < 2 * NA) {
                int j = g - NA; uint32_t row = j >> 2, c4 = j & 3;
                dst = stg + OFF_AL + swz(row, c4);
                srcp = Al + (size_t)row * as_ + kA + c4 * 8;
            } else if (g < 2 * NA + 512) {
                int j = g - 2 * NA; uint32_t row = j >> 2, c4 = j & 3;
                dst = stg + OFF_BH + swz(row, c4);
                srcp = Bh + (size_t)row * bs + kc + c4 * 8;
            } else {
                int j = g - 2 * NA - 512; uint32_t row = j >> 2, c4 = j & 3;
                dst = stg + OFF_BL + swz(row, c4);
                srcp = Bl + (size_t)row * bs + kc + c4 * 8;
            }
            CP_ASYNC16(dst, srcp);
        }
        CP_COMMIT();
    };

    issue(0);
    for (int c = 0; c < NCH; c++) {
        if (c + 1 < NCH) {
            issue(c + 1);
            asm volatile("cp.async.wait_group 1;" ::: "memory");
        } else {
            asm volatile("cp.async.wait_group 0;" ::: "memory");
        }
        __syncthreads();
        const uint32_t stg = sb + (uint32_t)(c & 1) * STAGE_B;
#pragma unroll
        for (int kk = 0; kk < 2; kk++) {
            uint32_t Ahf[MF][4], Alf[MF][4], Bhf[8][2], Blf[8][2];
            const uint32_t ac = (uint32_t)(kk * 2) + a_cbit;
            const uint32_t bc = (uint32_t)(kk * 2) + b_cbit;
#pragma unroll
            for (int mf = 0; mf < MF; mf++) {
                uint32_t ad = stg + OFF_AH + (uint32_t)(a_row + mf * 16) * 64u + ((ac ^ ax) << 4);
                LDSM_X4(Ahf[mf][0], Ahf[mf][1], Ahf[mf][2], Ahf[mf][3], ad);
                LDSM_X4(Alf[mf][0], Alf[mf][1], Alf[mf][2], Alf[mf][3], ad + A_TILE_B);
            }
#pragma unroll
            for (int nb = 0; nb < 4; nb++) {
                uint32_t bd = stg + OFF_BH + (uint32_t)(b_row + nb * 16) * 64u + ((bc ^ bx) << 4);
                LDSM_X4(Bhf[nb * 2][0], Bhf[nb * 2][1], Bhf[nb * 2 + 1][0], Bhf[nb * 2 + 1][1], bd);
                LDSM_X4(Blf[nb * 2][0], Blf[nb * 2][1], Blf[nb * 2 + 1][0], Blf[nb * 2 + 1][1], bd + B_TILE_B);
            }
#pragma unroll
            for (int mf = 0; mf < MF; mf++)
#pragma unroll
                for (int nf = 0; nf < 8; nf++) MMA_BF16(acc[mf][nf], Ahf[mf], Bhf[nf]);
#pragma unroll
            for (int mf = 0; mf < MF; mf++)
#pragma unroll
                for (int nf = 0; nf < 8; nf++) MMA_BF16(acc[mf][nf], Ahf[mf], Blf[nf]);
#pragma unroll
            for (int mf = 0; mf < MF; mf++)
#pragma unroll
                for (int nf = 0; nf < 8; nf++) MMA_BF16(acc[mf][nf], Alf[mf], Bhf[nf]);
        }
        __syncthreads();
    }

    // ---------------- epilogue ----------------
    const int quad = lane >> 2, tq = (lane & 3) * 2;
#pragma unroll
    for (int mf = 0; mf < MF; mf++) {
        const int rb = row0 + wm + mf * 16 + quad;
#pragma unroll
        for (int nf = 0; nf < 8; nf++) {
            const int n = n0 + wn + nf * 8 + tq;
#pragma unroll
            for (int half = 0; half < 2; half++) {
                const int m = rb + half * 8;
                const float c0 = acc[mf][nf][half * 2 + 0];
                const float c1 = acc[mf][nf][half * 2 + 1];
                if (kind == 0) {
                    float v0 = lrelu(c0 + b1[n]);
                    float v1 = lrelu(c1 + b1[n + 1]);
                    float h0 = __bfloat162float(__float2bfloat16(v0));
                    float h1 = __bfloat162float(__float2bfloat16(v1));
                    *(uint32_t*)(g_ah + (size_t)m * HD + n) = pack_bf2(h0, h1);
                    *(uint32_t*)(g_al + (size_t)m * HD + n) = pack_bf2(v0 - h0, v1 - h1);
                } else if (is_z) {
                    float2 zv = *(const float2*)(g_z[parity] + (size_t)m * ZD + n);
                    float2 ov = *(const float2*)(z0 + (size_t)m * ZD + n);
                    float v0 = lrelu(c0 + b2[n]) * r + zv.x;
                    float v1 = lrelu(c1 + b2[n + 1]) * r + zv.y;
                    *(float2*)(g_z[parity ^ 1] + (size_t)m * ZD + n) = make_float2(v0, v1);
                    *(float2*)(out + ((size_t)m * T + t) * ZD + n) = make_float2(v0 - ov.x, v1 - ov.y);
                    float h0 = __bfloat162float(__float2bfloat16(v0));
                    float h1 = __bfloat162float(__float2bfloat16(v1));
                    *(uint32_t*)(g_zh[parity ^ 1] + (size_t)m * ZD + n) = pack_bf2(h0, h1);
                    *(uint32_t*)(g_zl[parity ^ 1] + (size_t)m * ZD + n) = pack_bf2(v0 - h0, v1 - h1);
                } else {
                    const int nh = n - ZD;
                    float2 hv = *(const float2*)(g_h[parity] + (size_t)m * HD + nh);
                    float v0 = lrelu(c0 + b3[nh]) * r + hv.x;
                    float v1 = lrelu(c1 + b3[nh + 1]) * r + hv.y;
                    *(float2*)(g_h[parity ^ 1] + (size_t)m * HD + nh) = make_float2(v0, v1);
                    float h0 = __bfloat162float(__float2bfloat16(v0));
                    float h1 = __bfloat162float(__float2bfloat16(v1));
                    *(uint32_t*)(g_hh[parity ^ 1] + (size_t)m * HD + nh) = pack_bf2(h0, h1);
                    *(uint32_t*)(g_hl[parity ^ 1] + (size_t)m * HD + nh) = pack_bf2(v0 - h0, v1 - h1);
                }
            }
        }
    }
}

// ---------------- host ----------------
extern "C" void kernel_launch(void* const* d_in, const int* in_sizes, int n_in,
                              void* d_out, int out_size)
{
    const float* z  = (const float*)d_in[0];
    const float* h0 = (const float*)d_in[1];
    const float* W1 = (const float*)d_in[2];
    const float* b1 = (const float*)d_in[3];
    const float* W2 = (const float*)d_in[4];
    const float* b2 = (const float*)d_in[5];
    const float* W3 = (const float*)d_in[6];
    const float* b3 = (const float*)d_in[7];
    float* out = (float*)d_out;

    const int T = out_size / (BQ * ZD);
    const float r = 0.2f * 4.0f / (float)T;

    const int SM64 = 2 * (2 * 64 * 64 + 2 * 128 * 64);   // 49152
    const int SM32 = 2 * (2 * 32 * 64 + 2 * 128 * 64);   // 40960
    cudaFuncSetAttribute(rec_gemm<64>, cudaFuncAttributeMaxDynamicSharedMemorySize, SM64);
    cudaFuncSetAttribute(rec_gemm<32>, cudaFuncAttributeMaxDynamicSharedMemorySize, SM32);

    const int wtot = HD * ZD + ZD * KD2 + HD * KD2;
    prep_weights<<<(wtot + 255) / 256, 256>>>(W1, W2, W3);
    init_kernel<<<(BQ * ZD + 255) / 256, 256>>>(z, h0, out, T);

    int parity = 0;
    for (int t = 1; t < T; t++) {
        rec_gemm<32><<<dim3(HD / 128, BQ / 32), 128, SM32>>>(0, parity, t, r, b1, b2, b3, z, out, T);
        rec_gemm<64><<<dim3((ZD + HD) / 128, BQ / 64), 128, SM64>>>(1, parity, t, r, b1, b2, b3, z, out, T);
        parity ^= 1;
    }
}